// round 6
// baseline (speedup 1.0000x reference)
#include <cuda_runtime.h>
#include <math.h>
#include <stdint.h>

#define B_   2
#define P_   8192
#define NB_  24
#define C1_  32
#define C2_  32
#define K_   13
#define A_   12
#define CA_  384
#define NCHK_ 16                 // 24-ca chunks per k (g_WT layout granularity)
#define STEPS2_ 104              // 48-ca steps total (13 k x 8)

// smem float offsets
#define SA_F    0                // 2 stages x 128 x 52 = 13312
#define SB_F    13312            // 2 stages x 9216     = 18432
#define SACC_F  31744            // 128 x 196           = 25088
#define SMEM_FLOATS 56832        // 227328 bytes

// ---------------- device scratch ----------------
// g_WT: [k][nh][ch24][wn][cs][q][lane][4]  tf32-rounded
__device__ __align__(16) float g_WT[(size_t)K_*2*NCHK_*4608];
__device__ __align__(16) float g_md[B_*P_*3];
__device__ __align__(16) float g_kpo[C2_*K_*3];
__device__ __align__(16) float g_be[C2_*A_];

// ---------------- helpers ----------------
__device__ __forceinline__ float tf32r(float x) {
    uint32_t u; asm("cvt.rna.tf32.f32 %0, %1;" : "=r"(u) : "f"(x));
    return __uint_as_float(u);
}
__device__ __forceinline__ void cp16(void* dst, const void* src) {
    uint32_t a;
    asm("{ .reg .u64 t; cvta.to.shared.u64 t, %1; cvt.u32.u64 %0, t; }" : "=r"(a) : "l"(dst));
    asm volatile("cp.async.cg.shared.global [%0], [%1], 16;" :: "r"(a), "l"(src));
}
#define CP_COMMIT() asm volatile("cp.async.commit_group;" ::: "memory")
#define CP_WAIT0()  asm volatile("cp.async.wait_group 0;" ::: "memory")

__device__ __forceinline__ void mma8(float* d, const uint32_t* a, uint32_t b0, uint32_t b1) {
    asm volatile(
        "mma.sync.aligned.m16n8k8.row.col.f32.tf32.tf32.f32 "
        "{%0,%1,%2,%3}, {%4,%5,%6,%7}, {%8,%9}, {%0,%1,%2,%3};"
        : "+f"(d[0]), "+f"(d[1]), "+f"(d[2]), "+f"(d[3])
        : "r"(a[0]), "r"(a[1]), "r"(a[2]), "r"(a[3]), "r"(b0), "r"(b1));
}

// ---------------- prep kernels ----------------
__global__ void prep_small(const float* __restrict__ kpw, const float* __restrict__ vs,
                           const int* __restrict__ idx_map, const float* __restrict__ bias,
                           const int* __restrict__ lvl, const int* __restrict__ tivr) {
    int tid = threadIdx.x;
    if (tid < C2_*K_) {
        int d = tid / K_, k = tid % K_;
        float s0 = 0.f, s1 = 0.f, s2 = 0.f;
        for (int a = 0; a < A_; a++) {
            float w = kpw[d*36 + idx_map[k*A_ + a]];
            s0 += w * vs[a*3+0]; s1 += w * vs[a*3+1]; s2 += w * vs[a*3+2];
        }
        float inv = 1.0f / fmaxf(sqrtf(s0*s0 + s1*s1 + s2*s2), 1e-12f);
        g_kpo[tid*3+0] = s0*inv; g_kpo[tid*3+1] = s1*inv; g_kpo[tid*3+2] = s2*inv;
    }
    if (tid < C2_*A_) {
        int d = tid / A_, r = tid % A_;
        float be = 0.f;
        for (int k = 0; k < K_; k++) be += bias[d*5 + lvl[tivr[r*K_ + k]]];
        g_be[tid] = be;
    }
}

__global__ void mean_dir_kernel(const int* __restrict__ nbr, const float* __restrict__ vert) {
    int t = blockIdx.x * blockDim.x + threadIdx.x;
    if (t >= B_*P_) return;
    int b = t / P_;
    float vx = vert[t*3+0], vy = vert[t*3+1], vz = vert[t*3+2];
    float mx = 0.f, my = 0.f, mz = 0.f;
    const int* np = nbr + (size_t)t * NB_;
    const float* vb = vert + (size_t)b * P_ * 3;
    #pragma unroll 4
    for (int n = 0; n < NB_; n++) {
        int q = np[n];
        float dx = vb[q*3+0] - vx, dy = vb[q*3+1] - vy, dz = vb[q*3+2] - vz;
        float inv = 1.0f / fmaxf(sqrtf(dx*dx + dy*dy + dz*dz), 1e-12f);
        mx += dx*inv; my += dy*inv; mz += dz*inv;
    }
    const float s = 1.0f / (float)NB_;
    g_md[t*3+0] = mx*s; g_md[t*3+1] = my*s; g_md[t*3+2] = mz*s;
}

// WT -> g_WT[k][nh][ch][wn][cs][q][lane][e], tf32-rounded.
// logical-k permutation: physical j = 2t + (e&1); logical n = nf*8 + g, nf = 2q + (e>>1)
__global__ void prep_wt(const float* __restrict__ W, const float* __restrict__ kpw,
                        const int* __restrict__ idx_map, const int* __restrict__ tivr,
                        const int* __restrict__ tir) {
    int idx = blockIdx.x * 256 + threadIdx.x;
    if (idx >= K_*2*NCHK_*4608) return;
    int e    = idx & 3;  int u = idx >> 2;
    int lane = u & 31;   u >>= 5;
    int q    = u % 3;    u /= 3;
    int cs   = u % 3;    u /= 3;
    int wn   = u & 3;    u >>= 2;
    int ch   = u & 15;   u >>= 4;
    int nh   = u & 1;
    int k    = u >> 1;
    int g = lane >> 2, t = lane & 3;
    int nf = 2*q + (e >> 1);
    int ca = ch*24 + cs*8 + 2*t + (e & 1);
    int c = ca / A_, a = ca - c*A_;
    int n192 = wn*48 + nf*8 + g;
    int d = nh*16 + wn*4 + (g & 3);
    int r = (n192 % 48) >> 2;
    int m = idx_map[tivr[r*K_ + k]*A_ + tir[r*A_ + a]];
    g_WT[idx] = tf32r(W[(d*C1_ + c)*36 + m] * kpw[d*36 + m]);
}

// ---------------- main kernel ----------------
// grid = 256 = b(2) x ptile(64) x nh(2); block = 512 (wm = wid&3, wn = wid>>2)
__global__ void __launch_bounds__(512, 1)
main_kernel(const float* __restrict__ fm, float* __restrict__ out) {
    extern __shared__ float sm[];
    float* sA   = sm + SA_F;     // stage: 128 rows x 52 floats (48 data + 4 pad)
    float* sB   = sm + SB_F;     // stage: 9216 floats (two 24-ca chunks)
    float* sAcc = sm + SACC_F;   // 128 x 196

    const int tid  = threadIdx.x;
    const int wid  = tid >> 5;
    const int lane = tid & 31;
    const int wm = wid & 3, wn = wid >> 2;
    const int g = lane >> 2, t = lane & 3;
    const int nh = blockIdx.x & 1;
    const int pt = blockIdx.x >> 1;
    const int b  = pt >> 6;
    const int p0 = (pt & 63) << 7;

    for (int i = tid; i < 128*196; i += 512) sAcc[i] = 0.f;

    // mean_dir for this thread's 4 rows
    float md[2][2][3];
    #pragma unroll
    for (int mf = 0; mf < 2; mf++)
        #pragma unroll
        for (int h = 0; h < 2; h++) {
            int p = p0 + wm*32 + mf*16 + g + 8*h;
            const float* mp = g_md + ((size_t)b*P_ + p)*3;
            md[mf][h][0] = mp[0]; md[mf][h][1] = mp[1]; md[mf][h][2] = mp[2];
        }

    float part[2][6][4];
    #pragma unroll
    for (int mf = 0; mf < 2; mf++)
        #pragma unroll
        for (int nf = 0; nf < 6; nf++)
            #pragma unroll
            for (int c = 0; c < 4; c++) part[mf][nf][c] = 0.f;

    // ---- A loader: LDG -> cvt -> (later) STS; register double buffer ----
    const int clA = tid >> 7;      // 0..3 : c within 4-c chunk
    const int pA  = tid & 127;     // point row
    float rA[12];

    auto ldgA = [&](int s) {
        const int k = s >> 3, chp = s & 7;
        const float* src = fm + (((size_t)(b*C1_ + chp*4 + clA)*K_ + k)*P_ + p0 + pA)*A_;
        float4 v0 = ((const float4*)src)[0];
        float4 v1 = ((const float4*)src)[1];
        float4 v2 = ((const float4*)src)[2];
        rA[0]=tf32r(v0.x); rA[1]=tf32r(v0.y); rA[2] =tf32r(v0.z); rA[3] =tf32r(v0.w);
        rA[4]=tf32r(v1.x); rA[5]=tf32r(v1.y); rA[6] =tf32r(v1.z); rA[7] =tf32r(v1.w);
        rA[8]=tf32r(v2.x); rA[9]=tf32r(v2.y); rA[10]=tf32r(v2.z); rA[11]=tf32r(v2.w);
    };
    auto stsA = [&](int s) {
        float* d = sA + (s & 1)*6656 + pA*52 + clA*12;
        ((float4*)d)[0] = make_float4(rA[0], rA[1], rA[2],  rA[3]);
        ((float4*)d)[1] = make_float4(rA[4], rA[5], rA[6],  rA[7]);
        ((float4*)d)[2] = make_float4(rA[8], rA[9], rA[10], rA[11]);
    };
    auto cpB = [&](int s) {
        const int k = s >> 3, chp = s & 7;
        const float* src = g_WT + ((size_t)((k*2 + nh)*NCHK_ + chp*2))*4608;
        float* dst = sB + (s & 1)*9216;
        #pragma unroll
        for (int j = 0; j < 4; j++) {
            int u = tid + 512*j;
            cp16(dst + u*4, src + u*4);
        }
        {
            int u = tid + 2048;
            if (u < 2304) cp16(dst + u*4, src + u*4);
        }
    };

    // prologue
    ldgA(0); stsA(0);
    ldgA(1);
    cpB(0); CP_COMMIT();

    for (int s = 0; s < STEPS2_; s++) {
        CP_WAIT0();
        __syncthreads();

        if (s + 1 < STEPS2_) {
            stsA(s + 1);                       // stage (s+1)&1 — safe after barrier
            if (s + 2 < STEPS2_) ldgA(s + 2);  // refill regs
            cpB(s + 1);
            CP_COMMIT();
        }

        const int st = s & 1;
        const float2* A2 = (const float2*)(sA + st*6656);
        const float4* B4 = (const float4*)(sB + st*9216);
        const int r0 = (wm*32 + g)*26 + t;

        #pragma unroll
        for (int cs = 0; cs < 6; cs++) {
            uint32_t a[2][4];
            #pragma unroll
            for (int mf = 0; mf < 2; mf++) {
                float2 f0 = A2[r0 + mf*416 + cs*4];          // rows g,   cols (2t,2t+1)
                float2 f1 = A2[r0 + mf*416 + 208 + cs*4];    // rows g+8
                a[mf][0] = __float_as_uint(f0.x); a[mf][2] = __float_as_uint(f0.y);
                a[mf][1] = __float_as_uint(f1.x); a[mf][3] = __float_as_uint(f1.y);
            }
            const float4* Bq = B4 + (cs/3)*1152 + (wn*3 + cs%3)*96 + lane;
            float4 q0 = Bq[0], q1 = Bq[32], q2 = Bq[64];
            mma8(part[0][0], a[0], __float_as_uint(q0.x), __float_as_uint(q0.y));
            mma8(part[1][0], a[1], __float_as_uint(q0.x), __float_as_uint(q0.y));
            mma8(part[0][1], a[0], __float_as_uint(q0.z), __float_as_uint(q0.w));
            mma8(part[1][1], a[1], __float_as_uint(q0.z), __float_as_uint(q0.w));
            mma8(part[0][2], a[0], __float_as_uint(q1.x), __float_as_uint(q1.y));
            mma8(part[1][2], a[1], __float_as_uint(q1.x), __float_as_uint(q1.y));
            mma8(part[0][3], a[0], __float_as_uint(q1.z), __float_as_uint(q1.w));
            mma8(part[1][3], a[1], __float_as_uint(q1.z), __float_as_uint(q1.w));
            mma8(part[0][4], a[0], __float_as_uint(q2.x), __float_as_uint(q2.y));
            mma8(part[1][4], a[1], __float_as_uint(q2.x), __float_as_uint(q2.y));
            mma8(part[0][5], a[0], __float_as_uint(q2.z), __float_as_uint(q2.w));
            mma8(part[1][5], a[1], __float_as_uint(q2.z), __float_as_uint(q2.w));
        }

        if ((s & 7) == 7) {
            // per-k fold: acc += pw * part
            const int k = s >> 3;
            const int d0 = nh*16 + wn*4 + (t & 1)*2;
            float kp[2][3];
            #pragma unroll
            for (int e = 0; e < 2; e++) {
                const float* q = g_kpo + ((d0 + e)*K_ + k)*3;
                kp[e][0] = q[0]; kp[e][1] = q[1]; kp[e][2] = q[2];
            }
            float pw[2][2][2];
            #pragma unroll
            for (int mf = 0; mf < 2; mf++)
                #pragma unroll
                for (int h = 0; h < 2; h++)
                    #pragma unroll
                    for (int e = 0; e < 2; e++)
                        pw[mf][h][e] = fmaxf(md[mf][h][0]*kp[e][0] + md[mf][h][1]*kp[e][1]
                                           + md[mf][h][2]*kp[e][2], 0.f);
            #pragma unroll
            for (int mf = 0; mf < 2; mf++)
                #pragma unroll
                for (int nf = 0; nf < 6; nf++)
                    #pragma unroll
                    for (int c = 0; c < 4; c++) {
                        int h = c >> 1, e = c & 1;
                        int row = wm*32 + mf*16 + g + 8*h;
                        int col = wn*48 + nf*8 + 2*t + e;
                        sAcc[row*196 + col] += pw[mf][h][e] * part[mf][nf][c];
                        part[mf][nf][c] = 0.f;
                    }
        }
    }

    __syncthreads();

    // coalesced store: thread -> 4 (d,p) pairs, 12 contiguous floats each
    #pragma unroll
    for (int i = 0; i < 4; i++) {
        int pair = i*512 + tid;
        int p  = pair & 127;
        int dl = pair >> 7;
        int d  = nh*16 + dl;
        const float* ar = sAcc + p*196 + (dl >> 2)*48 + (dl & 3);
        float* op = out + (((size_t)b*C2_ + d)*P_ + p0 + p)*A_;
        float v[12];
        #pragma unroll
        for (int r = 0; r < 12; r++)
            v[r] = fmaxf(ar[r*4] + g_be[d*A_ + r], 0.f);
        reinterpret_cast<float4*>(op)[0] = make_float4(v[0], v[1], v[2],  v[3]);
        reinterpret_cast<float4*>(op)[1] = make_float4(v[4], v[5], v[6],  v[7]);
        reinterpret_cast<float4*>(op)[2] = make_float4(v[8], v[9], v[10], v[11]);
    }
}

// ---------------- launcher ----------------
extern "C" void kernel_launch(void* const* d_in, const int* in_sizes, int n_in,
                              void* d_out, int out_size) {
    const int*   nbr     = (const int*)  d_in[0];
    const float* vert    = (const float*)d_in[1];
    const float* fm      = (const float*)d_in[2];
    const float* W       = (const float*)d_in[3];
    const float* bias    = (const float*)d_in[4];
    const float* kpw     = (const float*)d_in[5];
    const float* vs      = (const float*)d_in[6];
    const int*   idx_map = (const int*)  d_in[7];
    const int*   tivr    = (const int*)  d_in[8];
    const int*   tir     = (const int*)  d_in[9];
    const int*   lvl     = (const int*)  d_in[10];
    float*       out     = (float*)d_out;

    prep_small<<<1, 512>>>(kpw, vs, idx_map, bias, lvl, tivr);
    prep_wt<<<(K_*2*NCHK_*4608 + 255)/256, 256>>>(W, kpw, idx_map, tivr, tir);
    mean_dir_kernel<<<(B_*P_ + 255)/256, 256>>>(nbr, vert);

    const int smem_bytes = SMEM_FLOATS * (int)sizeof(float);   // 227328
    cudaFuncSetAttribute(main_kernel, cudaFuncAttributeMaxDynamicSharedMemorySize, smem_bytes);
    main_kernel<<<256, 512, smem_bytes>>>(fm, out);
}

// round 7
// speedup vs baseline: 1.3056x; 1.3056x over previous
#include <cuda_runtime.h>
#include <cuda_fp16.h>
#include <math.h>
#include <stdint.h>

#define B_   2
#define P_   8192
#define NB_  24
#define C1_  32
#define C2_  32
#define K_   13
#define A_   12
#define STEPS2_ 104              // 48-ca steps (13 k x 8)
#define WT_HALVES (K_*2*8*9216)  // 1,916,928

// smem byte offsets
#define SA_B    0                // 2 stages x 128 x 56 halves = 28672 B
#define SB_B    28672            // 3 stages x 9216 halves     = 55296 B
#define SACC_B  83968            // 128 x 196 floats           = 100352 B
#define SMEM_BYTES 184320

// ---------------- device scratch ----------------
__device__ __align__(16) __half g_WTh[WT_HALVES];   // fp16 pre-packed B (3.8MB)
__device__ __align__(16) float g_md[B_*P_*3];
__device__ __align__(16) float g_kpo[C2_*K_*3];
__device__ __align__(16) float g_be[C2_*A_];

// ---------------- helpers ----------------
__device__ __forceinline__ void cp16(void* dst, const void* src) {
    uint32_t a;
    asm("{ .reg .u64 t; cvta.to.shared.u64 t, %1; cvt.u32.u64 %0, t; }" : "=r"(a) : "l"(dst));
    asm volatile("cp.async.cg.shared.global [%0], [%1], 16;" :: "r"(a), "l"(src));
}
#define CP_COMMIT() asm volatile("cp.async.commit_group;" ::: "memory")
#define CP_WAIT1()  asm volatile("cp.async.wait_group 1;" ::: "memory")

__device__ __forceinline__ void mma16(float* d, const uint32_t* a, uint32_t b0, uint32_t b1) {
    asm volatile(
        "mma.sync.aligned.m16n8k16.row.col.f32.f16.f16.f32 "
        "{%0,%1,%2,%3}, {%4,%5,%6,%7}, {%8,%9}, {%0,%1,%2,%3};"
        : "+f"(d[0]), "+f"(d[1]), "+f"(d[2]), "+f"(d[3])
        : "r"(a[0]), "r"(a[1]), "r"(a[2]), "r"(a[3]), "r"(b0), "r"(b1));
}
__device__ __forceinline__ uint32_t packh2(float x, float y) {
    uint32_t u;
    asm("cvt.rn.f16x2.f32 %0, %2, %1;" : "=r"(u) : "f"(x), "f"(y));  // y->hi, x->lo
    return u;
}

// ---------------- prep kernels ----------------
__global__ void prep_small(const float* __restrict__ kpw, const float* __restrict__ vs,
                           const int* __restrict__ idx_map, const float* __restrict__ bias,
                           const int* __restrict__ lvl, const int* __restrict__ tivr) {
    int tid = threadIdx.x;
    if (tid < C2_*K_) {
        int d = tid / K_, k = tid % K_;
        float s0 = 0.f, s1 = 0.f, s2 = 0.f;
        for (int a = 0; a < A_; a++) {
            float w = kpw[d*36 + idx_map[k*A_ + a]];
            s0 += w * vs[a*3+0]; s1 += w * vs[a*3+1]; s2 += w * vs[a*3+2];
        }
        float inv = 1.0f / fmaxf(sqrtf(s0*s0 + s1*s1 + s2*s2), 1e-12f);
        g_kpo[tid*3+0] = s0*inv; g_kpo[tid*3+1] = s1*inv; g_kpo[tid*3+2] = s2*inv;
    }
    if (tid < C2_*A_) {
        int d = tid / A_, r = tid % A_;
        float be = 0.f;
        for (int k = 0; k < K_; k++) be += bias[d*5 + lvl[tivr[r*K_ + k]]];
        g_be[tid] = be;
    }
}

__global__ void mean_dir_kernel(const int* __restrict__ nbr, const float* __restrict__ vert) {
    int t = blockIdx.x * blockDim.x + threadIdx.x;
    if (t >= B_*P_) return;
    int b = t / P_;
    float vx = vert[t*3+0], vy = vert[t*3+1], vz = vert[t*3+2];
    float mx = 0.f, my = 0.f, mz = 0.f;
    const int* np = nbr + (size_t)t * NB_;
    const float* vb = vert + (size_t)b * P_ * 3;
    #pragma unroll 4
    for (int n = 0; n < NB_; n++) {
        int q = np[n];
        float dx = vb[q*3+0] - vx, dy = vb[q*3+1] - vy, dz = vb[q*3+2] - vz;
        float inv = 1.0f / fmaxf(sqrtf(dx*dx + dy*dy + dz*dz), 1e-12f);
        mx += dx*inv; my += dy*inv; mz += dz*inv;
    }
    const float s = 1.0f / (float)NB_;
    g_md[t*3+0] = mx*s; g_md[t*3+1] = my*s; g_md[t*3+2] = mz*s;
}

// WT -> g_WTh[k][nh][sub][ks16][wn][j][lane][e], fp16.
// float4 unit = {b0(nf=2j), b1(nf=2j), b0(nf=2j+1), b1(nf=2j+1)} half2 pairs
// b0 halves: k_local = 2t, 2t+1 ; b1: 2t+8, 2t+9 ; B column = g
__global__ void prep_wt(const float* __restrict__ W, const float* __restrict__ kpw,
                        const int* __restrict__ idx_map, const int* __restrict__ tivr,
                        const int* __restrict__ tir) {
    int idx = blockIdx.x * 256 + threadIdx.x;
    if (idx >= WT_HALVES) return;
    int e    = idx & 7;  int u = idx >> 3;
    int lane = u & 31;   u >>= 5;
    int j    = u % 3;    u /= 3;
    int wn   = u & 3;    u >>= 2;
    int ks   = u % 3;    u /= 3;
    int sub  = u & 7;    u >>= 3;
    int nh   = u & 1;
    int k    = u >> 1;
    int g = lane >> 2, t = lane & 3;
    int nf   = 2*j + (e >> 2);
    int koff = e & 3;
    int ca = sub*48 + ks*16 + 2*t + (koff & 1) + 8*(koff >> 1);
    int c = ca / A_, a = ca - c*A_;
    int d = nh*16 + wn*4 + (g & 3);
    int r = (nf*8 + g) >> 2;
    int m = idx_map[tivr[r*K_ + k]*A_ + tir[r*A_ + a]];
    g_WTh[idx] = __float2half_rn(W[(d*C1_ + c)*36 + m] * kpw[d*36 + m]);
}

// ---------------- main kernel ----------------
// grid = 256 = b(2) x ptile(64) x nh(2); block = 512 (wm = wid&3, wn = wid>>2)
__global__ void __launch_bounds__(512, 1)
main_kernel(const float* __restrict__ fm, float* __restrict__ out) {
    extern __shared__ char smc[];
    float* sAcc = (float*)(smc + SACC_B);

    const int tid  = threadIdx.x;
    const int wid  = tid >> 5;
    const int lane = tid & 31;
    const int wm = wid & 3, wn = wid >> 2;
    const int g = lane >> 2, t = lane & 3;
    const int nh = blockIdx.x & 1;
    const int pt = blockIdx.x >> 1;
    const int b  = pt >> 6;
    const int p0 = (pt & 63) << 7;

    for (int i = tid; i < 128*196; i += 512) sAcc[i] = 0.f;

    float md[2][2][3];
    #pragma unroll
    for (int mf = 0; mf < 2; mf++)
        #pragma unroll
        for (int h = 0; h < 2; h++) {
            int p = p0 + wm*32 + mf*16 + g + 8*h;
            const float* mp = g_md + ((size_t)b*P_ + p)*3;
            md[mf][h][0] = mp[0]; md[mf][h][1] = mp[1]; md[mf][h][2] = mp[2];
        }

    float part[2][6][4];
    #pragma unroll
    for (int mf = 0; mf < 2; mf++)
        #pragma unroll
        for (int nf = 0; nf < 6; nf++)
            #pragma unroll
            for (int c = 0; c < 4; c++) part[mf][nf][c] = 0.f;

    // ---- A loader: LDG f32 -> pack half2 in regs -> STS ----
    const int clA = tid & 3;       // c within 4-c group
    const int pA  = tid >> 2;      // point row 0..127
    uint32_t hA[6];

    auto ldgA = [&](int s) {
        const int k = s >> 3, sub = s & 7;
        const float* src = fm + (((size_t)(b*C1_ + sub*4 + clA)*K_ + k)*P_ + p0 + pA)*A_;
        float4 v0 = ((const float4*)src)[0];
        float4 v1 = ((const float4*)src)[1];
        float4 v2 = ((const float4*)src)[2];
        hA[0] = packh2(v0.x, v0.y); hA[1] = packh2(v0.z, v0.w);
        hA[2] = packh2(v1.x, v1.y); hA[3] = packh2(v1.z, v1.w);
        hA[4] = packh2(v2.x, v2.y); hA[5] = packh2(v2.z, v2.w);
    };
    auto stsA = [&](int s) {
        char* d = smc + SA_B + (s & 1)*14336 + pA*112 + clA*24;
        ((uint2*)d)[0] = make_uint2(hA[0], hA[1]);
        ((uint2*)d)[1] = make_uint2(hA[2], hA[3]);
        ((uint2*)d)[2] = make_uint2(hA[4], hA[5]);
    };
    auto cpB = [&](int s) {
        const int k = s >> 3, sub = s & 7;
        const __half* src = g_WTh + ((size_t)((k*2 + nh)*8 + sub))*9216;
        char* dst = smc + SB_B + (s % 3)*18432;
        #pragma unroll
        for (int j = 0; j < 3; j++) {
            int u = tid + 512*j;
            if (u < 1152) cp16(dst + u*16, src + u*8);
        }
    };

    // prologue
    ldgA(0); stsA(0);
    ldgA(1);
    cpB(0); CP_COMMIT();
    cpB(1); CP_COMMIT();

    for (int s = 0; s < STEPS2_; s++) {
        CP_WAIT1();
        __syncthreads();

        if (s + 1 < STEPS2_) {
            stsA(s + 1);
            if (s + 2 < STEPS2_) ldgA(s + 2);
        }
        if (s + 2 < STEPS2_) cpB(s + 2);
        CP_COMMIT();

        const uint32_t* A0 = (const uint32_t*)(smc + SA_B + (s & 1)*14336) + (wm*32 + g)*28;
        const float4*   B4 = (const float4*)(smc + SB_B + (s % 3)*18432) + wn*96 + lane;

        #pragma unroll
        for (int ks = 0; ks < 3; ks++) {
            uint32_t a[2][4];
            #pragma unroll
            for (int mf = 0; mf < 2; mf++) {
                const uint32_t* Ar = A0 + mf*448 + ks*8 + t;
                a[mf][0] = Ar[0];
                a[mf][1] = Ar[224];
                a[mf][2] = Ar[4];
                a[mf][3] = Ar[228];
            }
            const float4* Bq = B4 + ks*384;
            float4 q0 = Bq[0], q1 = Bq[32], q2 = Bq[64];
            mma16(part[0][0], a[0], __float_as_uint(q0.x), __float_as_uint(q0.y));
            mma16(part[1][0], a[1], __float_as_uint(q0.x), __float_as_uint(q0.y));
            mma16(part[0][1], a[0], __float_as_uint(q0.z), __float_as_uint(q0.w));
            mma16(part[1][1], a[1], __float_as_uint(q0.z), __float_as_uint(q0.w));
            mma16(part[0][2], a[0], __float_as_uint(q1.x), __float_as_uint(q1.y));
            mma16(part[1][2], a[1], __float_as_uint(q1.x), __float_as_uint(q1.y));
            mma16(part[0][3], a[0], __float_as_uint(q1.z), __float_as_uint(q1.w));
            mma16(part[1][3], a[1], __float_as_uint(q1.z), __float_as_uint(q1.w));
            mma16(part[0][4], a[0], __float_as_uint(q2.x), __float_as_uint(q2.y));
            mma16(part[1][4], a[1], __float_as_uint(q2.x), __float_as_uint(q2.y));
            mma16(part[0][5], a[0], __float_as_uint(q2.z), __float_as_uint(q2.w));
            mma16(part[1][5], a[1], __float_as_uint(q2.z), __float_as_uint(q2.w));
        }

        if ((s & 7) == 7) {
            const int k = s >> 3;
            const int d0 = nh*16 + wn*4 + (t & 1)*2;
            float kp[2][3];
            #pragma unroll
            for (int e = 0; e < 2; e++) {
                const float* q = g_kpo + ((d0 + e)*K_ + k)*3;
                kp[e][0] = q[0]; kp[e][1] = q[1]; kp[e][2] = q[2];
            }
            float pw[2][2][2];
            #pragma unroll
            for (int mf = 0; mf < 2; mf++)
                #pragma unroll
                for (int h = 0; h < 2; h++)
                    #pragma unroll
                    for (int e = 0; e < 2; e++)
                        pw[mf][h][e] = fmaxf(md[mf][h][0]*kp[e][0] + md[mf][h][1]*kp[e][1]
                                           + md[mf][h][2]*kp[e][2], 0.f);
            #pragma unroll
            for (int mf = 0; mf < 2; mf++)
                #pragma unroll
                for (int nf = 0; nf < 6; nf++)
                    #pragma unroll
                    for (int c = 0; c < 4; c++) {
                        int h = c >> 1, e = c & 1;
                        int row = wm*32 + mf*16 + g + 8*h;
                        int col = wn*48 + nf*8 + 2*t + e;
                        sAcc[row*196 + col] += pw[mf][h][e] * part[mf][nf][c];
                        part[mf][nf][c] = 0.f;
                    }
        }
    }

    __syncthreads();

    // coalesced store: thread -> 4 (d,p) pairs, 12 contiguous floats each
    #pragma unroll
    for (int i = 0; i < 4; i++) {
        int pair = i*512 + tid;
        int p  = pair & 127;
        int dl = pair >> 7;
        int d  = nh*16 + dl;
        const float* ar = sAcc + p*196 + (dl >> 2)*48 + (dl & 3);
        float* op = out + (((size_t)b*C2_ + d)*P_ + p0 + p)*A_;
        float v[12];
        #pragma unroll
        for (int r = 0; r < 12; r++)
            v[r] = fmaxf(ar[r*4] + g_be[d*A_ + r], 0.f);
        reinterpret_cast<float4*>(op)[0] = make_float4(v[0], v[1], v[2],  v[3]);
        reinterpret_cast<float4*>(op)[1] = make_float4(v[4], v[5], v[6],  v[7]);
        reinterpret_cast<float4*>(op)[2] = make_float4(v[8], v[9], v[10], v[11]);
    }
}

// ---------------- launcher ----------------
extern "C" void kernel_launch(void* const* d_in, const int* in_sizes, int n_in,
                              void* d_out, int out_size) {
    const int*   nbr     = (const int*)  d_in[0];
    const float* vert    = (const float*)d_in[1];
    const float* fm      = (const float*)d_in[2];
    const float* W       = (const float*)d_in[3];
    const float* bias    = (const float*)d_in[4];
    const float* kpw     = (const float*)d_in[5];
    const float* vs      = (const float*)d_in[6];
    const int*   idx_map = (const int*)  d_in[7];
    const int*   tivr    = (const int*)  d_in[8];
    const int*   tir     = (const int*)  d_in[9];
    const int*   lvl     = (const int*)  d_in[10];
    float*       out     = (float*)d_out;

    prep_small<<<1, 512>>>(kpw, vs, idx_map, bias, lvl, tivr);
    prep_wt<<<(WT_HALVES + 255)/256, 256>>>(W, kpw, idx_map, tivr, tir);
    mean_dir_kernel<<<(B_*P_ + 255)/256, 256>>>(nbr, vert);

    cudaFuncSetAttribute(main_kernel, cudaFuncAttributeMaxDynamicSharedMemorySize, SMEM_BYTES);
    main_kernel<<<256, 512, SMEM_BYTES>>>(fm, out);
}

// round 8
// speedup vs baseline: 1.4065x; 1.0773x over previous
#include <cuda_runtime.h>
#include <cuda_fp16.h>
#include <math.h>
#include <stdint.h>

#define B_   2
#define P_   8192
#define NB_  24
#define C1_  32
#define C2_  32
#define K_   13
#define A_   12
#define STEPS2_ 104              // 48-ca steps (13 k x 8)
#define WT_HALVES (K_*2*8*9216)  // 1,916,928

// smem byte offsets
#define SA_B    0                // 2 stages x 128 x 56 halves = 28672 B
#define SB_B    28672            // 3 stages x 9216 halves     = 55296 B
#define SACC_B  83968            // 128 x 196 floats           = 100352 B
#define SMEM_BYTES 184320

// ---------------- device scratch ----------------
__device__ __align__(16) __half g_WTh[WT_HALVES];   // fp16 pre-packed B (3.8MB)
__device__ __align__(16) float g_md[B_*P_*3];
__device__ __align__(16) float g_kpo[C2_*K_*3];
__device__ __align__(16) float g_be[C2_*A_];

// ---------------- helpers ----------------
__device__ __forceinline__ void cp16(void* dst, const void* src) {
    uint32_t a;
    asm("{ .reg .u64 t; cvta.to.shared.u64 t, %1; cvt.u32.u64 %0, t; }" : "=r"(a) : "l"(dst));
    asm volatile("cp.async.cg.shared.global [%0], [%1], 16;" :: "r"(a), "l"(src));
}
#define CP_COMMIT() asm volatile("cp.async.commit_group;" ::: "memory")
#define CP_WAIT1()  asm volatile("cp.async.wait_group 1;" ::: "memory")

__device__ __forceinline__ void mma16(float* d, const uint32_t* a, uint32_t b0, uint32_t b1) {
    asm volatile(
        "mma.sync.aligned.m16n8k16.row.col.f32.f16.f16.f32 "
        "{%0,%1,%2,%3}, {%4,%5,%6,%7}, {%8,%9}, {%0,%1,%2,%3};"
        : "+f"(d[0]), "+f"(d[1]), "+f"(d[2]), "+f"(d[3])
        : "r"(a[0]), "r"(a[1]), "r"(a[2]), "r"(a[3]), "r"(b0), "r"(b1));
}
__device__ __forceinline__ uint32_t packh2(float x, float y) {
    uint32_t u;
    asm("cvt.rn.f16x2.f32 %0, %2, %1;" : "=r"(u) : "f"(x), "f"(y));  // y->hi, x->lo
    return u;
}

// ---------------- prep kernels ----------------
__global__ void prep_small(const float* __restrict__ kpw, const float* __restrict__ vs,
                           const int* __restrict__ idx_map, const float* __restrict__ bias,
                           const int* __restrict__ lvl, const int* __restrict__ tivr) {
    int tid = threadIdx.x;
    if (tid < C2_*K_) {
        int d = tid / K_, k = tid % K_;
        float s0 = 0.f, s1 = 0.f, s2 = 0.f;
        for (int a = 0; a < A_; a++) {
            float w = kpw[d*36 + idx_map[k*A_ + a]];
            s0 += w * vs[a*3+0]; s1 += w * vs[a*3+1]; s2 += w * vs[a*3+2];
        }
        float inv = 1.0f / fmaxf(sqrtf(s0*s0 + s1*s1 + s2*s2), 1e-12f);
        g_kpo[tid*3+0] = s0*inv; g_kpo[tid*3+1] = s1*inv; g_kpo[tid*3+2] = s2*inv;
    }
    if (tid < C2_*A_) {
        int d = tid / A_, r = tid % A_;
        float be = 0.f;
        for (int k = 0; k < K_; k++) be += bias[d*5 + lvl[tivr[r*K_ + k]]];
        g_be[tid] = be;
    }
}

__global__ void mean_dir_kernel(const int* __restrict__ nbr, const float* __restrict__ vert) {
    int t = blockIdx.x * blockDim.x + threadIdx.x;
    if (t >= B_*P_) return;
    int b = t / P_;
    float vx = vert[t*3+0], vy = vert[t*3+1], vz = vert[t*3+2];
    float mx = 0.f, my = 0.f, mz = 0.f;
    const int* np = nbr + (size_t)t * NB_;
    const float* vb = vert + (size_t)b * P_ * 3;
    #pragma unroll 4
    for (int n = 0; n < NB_; n++) {
        int q = np[n];
        float dx = vb[q*3+0] - vx, dy = vb[q*3+1] - vy, dz = vb[q*3+2] - vz;
        float inv = 1.0f / fmaxf(sqrtf(dx*dx + dy*dy + dz*dz), 1e-12f);
        mx += dx*inv; my += dy*inv; mz += dz*inv;
    }
    const float s = 1.0f / (float)NB_;
    g_md[t*3+0] = mx*s; g_md[t*3+1] = my*s; g_md[t*3+2] = mz*s;
}

// WT -> g_WTh[k][nh][sub][ks16][wn][j][lane][e], fp16.  (unchanged from R7)
__global__ void prep_wt(const float* __restrict__ W, const float* __restrict__ kpw,
                        const int* __restrict__ idx_map, const int* __restrict__ tivr,
                        const int* __restrict__ tir) {
    int idx = blockIdx.x * 256 + threadIdx.x;
    if (idx >= WT_HALVES) return;
    int e    = idx & 7;  int u = idx >> 3;
    int lane = u & 31;   u >>= 5;
    int j    = u % 3;    u /= 3;
    int wn   = u & 3;    u >>= 2;
    int ks   = u % 3;    u /= 3;
    int sub  = u & 7;    u >>= 3;
    int nh   = u & 1;
    int k    = u >> 1;
    int g = lane >> 2, t = lane & 3;
    int nf   = 2*j + (e >> 2);
    int koff = e & 3;
    int ca = sub*48 + ks*16 + 2*t + (koff & 1) + 8*(koff >> 1);
    int c = ca / A_, a = ca - c*A_;
    int d = nh*16 + wn*4 + (g & 3);
    int r = (nf*8 + g) >> 2;
    int m = idx_map[tivr[r*K_ + k]*A_ + tir[r*A_ + a]];
    g_WTh[idx] = __float2half_rn(W[(d*C1_ + c)*36 + m] * kpw[d*36 + m]);
}

// ---------------- main kernel ----------------
// grid = 256 = b(2) x ptile(64) x nh(2); block = 1024 (32 warps: wm = wid&7, wn = wid>>3)
__global__ void __launch_bounds__(1024, 1)
main_kernel(const float* __restrict__ fm, float* __restrict__ out) {
    extern __shared__ char smc[];
    float* sAcc = (float*)(smc + SACC_B);

    const int tid  = threadIdx.x;
    const int wid  = tid >> 5;
    const int lane = tid & 31;
    const int wm = wid & 7, wn = wid >> 3;     // wm: 16-row group, wn: 48-col group
    const int g = lane >> 2, t = lane & 3;
    const int nh = blockIdx.x & 1;
    const int pt = blockIdx.x >> 1;
    const int b  = pt >> 6;
    const int p0 = (pt & 63) << 7;

    for (int i = tid; i < 128*196; i += 1024) sAcc[i] = 0.f;

    // mean_dir for this thread's 2 rows (g, g+8 within the 16-row warp tile)
    float md[2][3];
    #pragma unroll
    for (int h = 0; h < 2; h++) {
        int p = p0 + wm*16 + g + 8*h;
        const float* mp = g_md + ((size_t)b*P_ + p)*3;
        md[h][0] = mp[0]; md[h][1] = mp[1]; md[h][2] = mp[2];
    }

    float part[6][4];
    #pragma unroll
    for (int nf = 0; nf < 6; nf++)
        #pragma unroll
        for (int c = 0; c < 4; c++) part[nf][c] = 0.f;

    // ---- A loader (threads 0..511): LDG f32 -> pack half2 -> STS ----
    const int clA = tid & 3;       // c within 4-c group
    const int pA  = tid >> 2;      // point row 0..127 (for tid<512)
    const bool aActive = (tid < 512);
    uint32_t hA[6];

    auto ldgA = [&](int s) {
        if (!aActive) return;
        const int k = s >> 3, sub = s & 7;
        const float* src = fm + (((size_t)(b*C1_ + sub*4 + clA)*K_ + k)*P_ + p0 + pA)*A_;
        float4 v0 = ((const float4*)src)[0];
        float4 v1 = ((const float4*)src)[1];
        float4 v2 = ((const float4*)src)[2];
        hA[0] = packh2(v0.x, v0.y); hA[1] = packh2(v0.z, v0.w);
        hA[2] = packh2(v1.x, v1.y); hA[3] = packh2(v1.z, v1.w);
        hA[4] = packh2(v2.x, v2.y); hA[5] = packh2(v2.z, v2.w);
    };
    auto stsA = [&](int s) {
        if (!aActive) return;
        char* d = smc + SA_B + (s & 1)*14336 + pA*112 + clA*24;
        ((uint2*)d)[0] = make_uint2(hA[0], hA[1]);
        ((uint2*)d)[1] = make_uint2(hA[2], hA[3]);
        ((uint2*)d)[2] = make_uint2(hA[4], hA[5]);
    };
    auto cpB = [&](int s) {
        const int k = s >> 3, sub = s & 7;
        const __half* src = g_WTh + ((size_t)((k*2 + nh)*8 + sub))*9216;
        char* dst = smc + SB_B + (s % 3)*18432;
        if (tid < 1024) cp16(dst + tid*16, src + tid*8);
        {
            int u = tid + 1024;
            if (u < 1152) cp16(dst + u*16, src + u*8);
        }
    };

    // prologue
    ldgA(0); stsA(0);
    ldgA(1);
    cpB(0); CP_COMMIT();
    cpB(1); CP_COMMIT();

    for (int s = 0; s < STEPS2_; s++) {
        CP_WAIT1();
        __syncthreads();

        if (s + 1 < STEPS2_) {
            stsA(s + 1);
            if (s + 2 < STEPS2_) ldgA(s + 2);
        }
        if (s + 2 < STEPS2_) cpB(s + 2);
        CP_COMMIT();

        const uint32_t* A0 = (const uint32_t*)(smc + SA_B + (s & 1)*14336) + (wm*16 + g)*28;
        const float4*   B4 = (const float4*)(smc + SB_B + (s % 3)*18432) + wn*96 + lane;

        #pragma unroll
        for (int ks = 0; ks < 3; ks++) {
            uint32_t a[4];
            {
                const uint32_t* Ar = A0 + ks*8 + t;
                a[0] = Ar[0];
                a[1] = Ar[224];      // +8 rows
                a[2] = Ar[4];
                a[3] = Ar[228];
            }
            const float4* Bq = B4 + ks*384;
            float4 q0 = Bq[0], q1 = Bq[32], q2 = Bq[64];
            mma16(part[0], a, __float_as_uint(q0.x), __float_as_uint(q0.y));
            mma16(part[1], a, __float_as_uint(q0.z), __float_as_uint(q0.w));
            mma16(part[2], a, __float_as_uint(q1.x), __float_as_uint(q1.y));
            mma16(part[3], a, __float_as_uint(q1.z), __float_as_uint(q1.w));
            mma16(part[4], a, __float_as_uint(q2.x), __float_as_uint(q2.y));
            mma16(part[5], a, __float_as_uint(q2.z), __float_as_uint(q2.w));
        }

        if ((s & 7) == 7) {
            const int k = s >> 3;
            const int d0 = nh*16 + wn*4 + (t & 1)*2;
            float kp[2][3];
            #pragma unroll
            for (int e = 0; e < 2; e++) {
                const float* q = g_kpo + ((d0 + e)*K_ + k)*3;
                kp[e][0] = q[0]; kp[e][1] = q[1]; kp[e][2] = q[2];
            }
            float pw[2][2];
            #pragma unroll
            for (int h = 0; h < 2; h++)
                #pragma unroll
                for (int e = 0; e < 2; e++)
                    pw[h][e] = fmaxf(md[h][0]*kp[e][0] + md[h][1]*kp[e][1]
                                   + md[h][2]*kp[e][2], 0.f);
            #pragma unroll
            for (int nf = 0; nf < 6; nf++)
                #pragma unroll
                for (int c = 0; c < 4; c++) {
                    int h = c >> 1, e = c & 1;
                    int row = wm*16 + g + 8*h;
                    int col = wn*48 + nf*8 + 2*t + e;
                    sAcc[row*196 + col] += pw[h][e] * part[nf][c];
                    part[nf][c] = 0.f;
                }
        }
    }

    __syncthreads();

    // coalesced store: thread -> 2 (d,p) pairs, 12 contiguous floats each
    #pragma unroll
    for (int i = 0; i < 2; i++) {
        int pair = i*1024 + tid;
        int p  = pair & 127;
        int dl = pair >> 7;
        int d  = nh*16 + dl;
        const float* ar = sAcc + p*196 + (dl >> 2)*48 + (dl & 3);
        float* op = out + (((size_t)b*C2_ + d)*P_ + p0 + p)*A_;
        float v[12];
        #pragma unroll
        for (int r = 0; r < 12; r++)
            v[r] = fmaxf(ar[r*4] + g_be[d*A_ + r], 0.f);
        reinterpret_cast<float4*>(op)[0] = make_float4(v[0], v[1], v[2],  v[3]);
        reinterpret_cast<float4*>(op)[1] = make_float4(v[4], v[5], v[6],  v[7]);
        reinterpret_cast<float4*>(op)[2] = make_float4(v[8], v[9], v[10], v[11]);
    }
}

// ---------------- launcher ----------------
extern "C" void kernel_launch(void* const* d_in, const int* in_sizes, int n_in,
                              void* d_out, int out_size) {
    const int*   nbr     = (const int*)  d_in[0];
    const float* vert    = (const float*)d_in[1];
    const float* fm      = (const float*)d_in[2];
    const float* W       = (const float*)d_in[3];
    const float* bias    = (const float*)d_in[4];
    const float* kpw     = (const float*)d_in[5];
    const float* vs      = (const float*)d_in[6];
    const int*   idx_map = (const int*)  d_in[7];
    const int*   tivr    = (const int*)  d_in[8];
    const int*   tir     = (const int*)  d_in[9];
    const int*   lvl     = (const int*)  d_in[10];
    float*       out     = (float*)d_out;

    prep_small<<<1, 512>>>(kpw, vs, idx_map, bias, lvl, tivr);
    prep_wt<<<(WT_HALVES + 255)/256, 256>>>(W, kpw, idx_map, tivr, tir);
    mean_dir_kernel<<<(B_*P_ + 255)/256, 256>>>(nbr, vert);

    cudaFuncSetAttribute(main_kernel, cudaFuncAttributeMaxDynamicSharedMemorySize, SMEM_BYTES);
    main_kernel<<<256, 1024, SMEM_BYTES>>>(fm, out);
}